// round 15
// baseline (speedup 1.0000x reference)
#include <cuda_runtime.h>
#include <cstdint>

// APPLY_PENALTY — TERMINAL kernel (floor confirmed, R3–R14).
//
// dur_us = compulsory DRAM traffic / sustained mixed R/W bandwidth
//        = (131 MB read + 131 MB write) / ~5.8 TB/s ≈ 45 us.
// Every copy mechanism on this part (LDG.128/.256, streaming / pinned /
// write-through L2 policies, TMA bulk DMA, CE memcpy) is equivalent at this
// floor. The single structural win was fusing the penalty scatter into the
// copy (49.2 -> 44.7 us). Best-measured variant below.
//
// Problem constants (fixed for this instance):
//   logits:  [B=256, VOCAB=128000] float32
//   save_id: [B=256, HIST=512] int32 (JAX x64 disabled -> int64 decays to int32)
//   penalty_value: [1] float32
//   penalty_range: 64
#define B_DIM      256
#define VOCAB_DIM  128000
#define HIST_DIM   512
#define PEN_RANGE  64

// Row = 32000 float4. Split into 25 segments of 1280 float4 (5120 floats).
#define ROW_F4        32000
#define SEGS_PER_ROW  25
#define SEG_F4        1280
#define SEG_FLOATS    (SEG_F4 * 4)   // 5120
#define THREADS       256
#define F4_PER_THREAD 5              // 256 * 5 = 1280

// Fused copy + penalty fixup. Streaming (evict-first) hints on the bulk
// streams; all 5 loads front-batched for per-warp MLP before the 5 stores.
__global__ void __launch_bounds__(THREADS)
apply_penalty_fused(const float4* __restrict__ logits4,
                    const float*  __restrict__ logits,
                    const int*    __restrict__ save_id,
                    const float*  __restrict__ penalty,
                    float4* __restrict__ out4,
                    float*  __restrict__ out) {
    const int b   = blockIdx.x;
    const int row = b / SEGS_PER_ROW;
    const int seg = b - row * SEGS_PER_ROW;

    // ---- copy phase: batch all 5 loads, then all 5 stores (streaming) ----
    const size_t base4 = (size_t)row * ROW_F4 + (size_t)seg * SEG_F4 + threadIdx.x;
    float4 v[F4_PER_THREAD];
    #pragma unroll
    for (int i = 0; i < F4_PER_THREAD; i++)
        v[i] = __ldcs(&logits4[base4 + (size_t)i * THREADS]);
    #pragma unroll
    for (int i = 0; i < F4_PER_THREAD; i++)
        __stcs(&out4[base4 + (size_t)i * THREADS], v[i]);

    __syncthreads();   // copy stores ordered before fixup stores (block scope)

    // ---- fixup phase: threads 0..63 check this row's 64 penalized ids ----
    // Only ids inside this block's segment are rewritten. The penalized value
    // depends only on the ORIGINAL logit, so duplicate ids are idempotent.
    if (threadIdx.x < PEN_RANGE) {
        const int lo = seg * SEG_FLOATS;
        const int hi = lo + SEG_FLOATS;
        int id = save_id[row * HIST_DIM + (HIST_DIM - PEN_RANGE) + threadIdx.x];
        if (id >= lo && id < hi) {
            const float p = penalty[0];
            size_t off = (size_t)row * VOCAB_DIM + (size_t)id;
            out[off] = logits[off] * p;   // L2-hit read; tiny scattered store
        }
    }
}

extern "C" void kernel_launch(void* const* d_in, const int* in_sizes, int n_in,
                              void* d_out, int out_size) {
    const float* logits  = (const float*)d_in[0];
    const int*   save_id = (const int*)d_in[1];
    const float* penalty = (const float*)d_in[2];
    float*       out     = (float*)d_out;

    const int blocks = B_DIM * SEGS_PER_ROW;   // 6400 blocks x 256 threads
    apply_penalty_fused<<<blocks, THREADS>>>(
        (const float4*)logits, logits, save_id, penalty,
        (float4*)out, out);
}

// round 16
// speedup vs baseline: 1.0050x; 1.0050x over previous
#include <cuda_runtime.h>
#include <cstdint>

// APPLY_PENALTY — TERMINAL kernel (DRAM floor confirmed, R3–R15).
//
// dur_us = compulsory DRAM traffic / sustained mixed R/W bandwidth
//        = (131 MB read + 131 MB write) / ~5.8 TB/s ≈ 45 us.
// Every copy mechanism on this part (LDG.128/.256, streaming / pinned /
// write-through L2 policies, TMA bulk DMA, CE memcpy) is equivalent at this
// floor. The single structural win was fusing the penalty scatter into the
// copy (49.2 -> 44.7 us). Best-measured variant below (44.74 us best obs,
// ~44.97 us mean over six runs).
//
// Problem constants (fixed for this instance):
//   logits:  [B=256, VOCAB=128000] float32
//   save_id: [B=256, HIST=512] int32 (JAX x64 disabled -> int64 decays to int32)
//   penalty_value: [1] float32
//   penalty_range: 64
#define B_DIM      256
#define VOCAB_DIM  128000
#define HIST_DIM   512
#define PEN_RANGE  64

// Row = 32000 float4. Split into 25 segments of 1280 float4 (5120 floats).
#define ROW_F4        32000
#define SEGS_PER_ROW  25
#define SEG_F4        1280
#define SEG_FLOATS    (SEG_F4 * 4)   // 5120
#define THREADS       256
#define F4_PER_THREAD 5              // 256 * 5 = 1280

// Fused copy + penalty fixup. Streaming (evict-first) hints on the bulk
// streams; all 5 loads front-batched for per-warp MLP before the 5 stores.
__global__ void __launch_bounds__(THREADS)
apply_penalty_fused(const float4* __restrict__ logits4,
                    const float*  __restrict__ logits,
                    const int*    __restrict__ save_id,
                    const float*  __restrict__ penalty,
                    float4* __restrict__ out4,
                    float*  __restrict__ out) {
    const int b   = blockIdx.x;
    const int row = b / SEGS_PER_ROW;
    const int seg = b - row * SEGS_PER_ROW;

    // ---- copy phase: batch all 5 loads, then all 5 stores (streaming) ----
    const size_t base4 = (size_t)row * ROW_F4 + (size_t)seg * SEG_F4 + threadIdx.x;
    float4 v[F4_PER_THREAD];
    #pragma unroll
    for (int i = 0; i < F4_PER_THREAD; i++)
        v[i] = __ldcs(&logits4[base4 + (size_t)i * THREADS]);
    #pragma unroll
    for (int i = 0; i < F4_PER_THREAD; i++)
        __stcs(&out4[base4 + (size_t)i * THREADS], v[i]);

    __syncthreads();   // copy stores ordered before fixup stores (block scope)

    // ---- fixup phase: threads 0..63 check this row's 64 penalized ids ----
    // Only ids inside this block's segment are rewritten. The penalized value
    // depends only on the ORIGINAL logit, so duplicate ids are idempotent.
    if (threadIdx.x < PEN_RANGE) {
        const int lo = seg * SEG_FLOATS;
        const int hi = lo + SEG_FLOATS;
        int id = save_id[row * HIST_DIM + (HIST_DIM - PEN_RANGE) + threadIdx.x];
        if (id >= lo && id < hi) {
            const float p = penalty[0];
            size_t off = (size_t)row * VOCAB_DIM + (size_t)id;
            out[off] = logits[off] * p;   // L2-hit read; tiny scattered store
        }
    }
}

extern "C" void kernel_launch(void* const* d_in, const int* in_sizes, int n_in,
                              void* d_out, int out_size) {
    const float* logits  = (const float*)d_in[0];
    const int*   save_id = (const int*)d_in[1];
    const float* penalty = (const float*)d_in[2];
    float*       out     = (float*)d_out;

    const int blocks = B_DIM * SEGS_PER_ROW;   // 6400 blocks x 256 threads
    apply_penalty_fused<<<blocks, THREADS>>>(
        (const float4*)logits, logits, save_id, penalty,
        (float4*)out, out);
}